// round 8
// baseline (speedup 1.0000x reference)
#include <cuda_runtime.h>
#include <cuda_fp16.h>
#include <math_constants.h>
#include <cstdint>

// ---------------- problem constants ----------------
#define B_  4
#define T_  1024
#define M_  4096          // B*T tokens
#define H_  2048
#define V_  32000

// ---------------- GEMM tiling ----------------
#define TM  128           // CTA M tile
#define TN  256           // CTA N tile
#define KCH 32            // K elements (halfs) per smem stage
#define NSTEPS (H_/KCH)   // 64
#define NSTAGE 3
#define GRIDM (M_/TM)     // 32
#define GRIDN (V_/TN)     // 125
#define NTN 1000          // 32-col LSE partial tiles (V/32)

#define SA  20            // smem row stride in 32-bit words (16 data + 4 pad)
#define A_BYTES (128*SA*4)        // 10240
#define B_BYTES (256*SA*4)        // 20480
#define STAGE_BYTES (A_BYTES + B_BYTES)   // 30720
#define STAGE_WORDS (STAGE_BYTES/4)
#define SM_BIAS (NSTAGE*STAGE_BYTES)      // bias after the 3-stage ring
#define SMEM_TOTAL (SM_BIAS + 256*4)      // 93184

// ---------------- scratch (no allocations allowed) ----------------
__device__ int    g_is64;
__device__ __half g_Xh[(size_t)M_ * H_];   // fp16 activation copy (16 MB)
__device__ float  g_pmax[(size_t)M_ * NTN];
__device__ float  g_psum[(size_t)M_ * NTN];
__device__ float  g_tok [M_];
__device__ float  g_losspt[M_];
__device__ float  g_klpt  [M_];
__device__ float  g_clippt[M_];
__device__ float  g_maskpt[M_];

// ---------------- kernel 0: detect int32 vs int64 input_id ----------------
__global__ void detect_id64_kernel(const int* __restrict__ idw) {
    __shared__ int bad;
    if (threadIdx.x == 0) bad = 0;
    __syncthreads();
    int local = 0;
    for (int i = threadIdx.x; i < 2048; i += blockDim.x)
        if (idw[2 * i + 1] != 0) local = 1;
    if (local) atomicOr(&bad, 1);
    __syncthreads();
    if (threadIdx.x == 0) g_is64 = bad ? 0 : 1;
}

// ---------------- kernel 0a: fp32 -> fp16 conversion (X only, 8 elems/thread) ----------------
__global__ void convert_half_kernel(const float* __restrict__ src,
                                    __half* __restrict__ dst, int n8)
{
    const int i = blockIdx.x * blockDim.x + threadIdx.x;
    if (i >= n8) return;
    const float4* s = (const float4*)src + 2 * i;
    float4 a = s[0], b = s[1];
    __half2 h[4];
    h[0] = __floats2half2_rn(a.x, a.y);
    h[1] = __floats2half2_rn(a.z, a.w);
    h[2] = __floats2half2_rn(b.x, b.y);
    h[3] = __floats2half2_rn(b.z, b.w);
    *(uint4*)((__half2*)dst + 4 * (size_t)i) = *(uint4*)h;
}

// ---------------- kernel 0b: exact fp32 target-token logits ----------------
__global__ void tok_logit_kernel(const float* __restrict__ X,
                                 const float* __restrict__ W,
                                 const float* __restrict__ bias,
                                 const void* __restrict__ idptr)
{
    const int warp = threadIdx.x >> 5, lane = threadIdx.x & 31;
    const int t = blockIdx.x * 8 + warp;
    if (t >= M_) return;
    const int vid = g_is64 ? (int)((const long long*)idptr)[t]
                           : ((const int*)idptr)[t];
    const float4* xr = (const float4*)(X + (size_t)t * H_);
    const float4* wr = (const float4*)(W + (size_t)vid * H_);
    float s = 0.f;
#pragma unroll 4
    for (int i = lane; i < H_ / 4; i += 32) {
        float4 a = xr[i], b = wr[i];
        s += a.x * b.x + a.y * b.y + a.z * b.z + a.w * b.w;
    }
#pragma unroll
    for (int o = 16; o; o >>= 1) s += __shfl_xor_sync(0xffffffffu, s, o);
    if (lane == 0) g_tok[t] = s + bias[vid];
}

// ---------------- ptx helpers ----------------
__device__ __forceinline__ void mma_f16(float* d, const uint32_t* a, const uint32_t* b) {
    asm volatile(
        "mma.sync.aligned.m16n8k16.row.col.f32.f16.f16.f32 "
        "{%0,%1,%2,%3}, {%4,%5,%6,%7}, {%8,%9}, {%0,%1,%2,%3};"
        : "+f"(d[0]), "+f"(d[1]), "+f"(d[2]), "+f"(d[3])
        : "r"(a[0]), "r"(a[1]), "r"(a[2]), "r"(a[3]), "r"(b[0]), "r"(b[1]));
}
__device__ __forceinline__ uint32_t cvta_smem(const void* p) {
    uint32_t a;
    asm("{ .reg .u64 t; cvta.to.shared.u64 t, %1; cvt.u32.u64 %0, t; }" : "=r"(a) : "l"(p));
    return a;
}
__device__ __forceinline__ void cp16(uint32_t dst, const void* src) {
    asm volatile("cp.async.cg.shared.global [%0], [%1], 16;" :: "r"(dst), "l"(src));
}
__device__ __forceinline__ void cp_commit() {
    asm volatile("cp.async.commit_group;" ::: "memory");
}
__device__ __forceinline__ void cp_wait1() {
    asm volatile("cp.async.wait_group 1;" ::: "memory");
}
// convert 8 fp32 (two float4) -> uint4 of 8 halfs (cvt.rn, same as convert kernel)
__device__ __forceinline__ uint4 pack_half8(float4 a, float4 b) {
    __half2 h[4];
    h[0] = __floats2half2_rn(a.x, a.y);
    h[1] = __floats2half2_rn(a.z, a.w);
    h[2] = __floats2half2_rn(b.x, b.y);
    h[3] = __floats2half2_rn(b.z, b.w);
    return *(uint4*)h;
}

// ---------------- kernel 1: fp16 mma GEMM + streaming LSE ----------------
// 512 threads (16 warps, warp tile 64x32), 3-stage pipeline.
// A: cp.async from pre-converted g_Xh. B: LDG fp32 W + in-register cvt + STS
// (removes the 393MB W-convert pass; halfs are bitwise identical).
__global__ void __launch_bounds__(512, 1)
gemm_lse_mma(const float* __restrict__ W, const float* __restrict__ bias)
{
    extern __shared__ char smem[];
    float* sbias = (float*)(smem + SM_BIAS);
    const uint32_t sb = cvta_smem(smem);

    const int tid = threadIdx.x, wid = tid >> 5, lid = tid & 31;
    const int g = lid >> 2, c = lid & 3;
    const int m0 = blockIdx.x * TM, n0 = blockIdx.y * TN;
    const int wm = (wid & 1) * 64;       // warp M offset (0/64)
    const int wni = wid >> 1;            // 0..7
    const int wn = wni * 32;             // warp N offset

    if (tid < 256) sbias[tid] = bias[n0 + tid];

    // A producer (cp.async, 16B = 8 halfs): 128 rows x 4 chunks = 512 -> 1/thread
    const __half* gA0;  uint32_t dA0;
    {
        int r = tid >> 2, c4 = tid & 3;
        gA0 = g_Xh + (size_t)(m0 + r) * H_ + c4 * 8;
        dA0 = (uint32_t)(r * SA + c4 * 4) * 4u;
    }
    // B producer (fp32 LDG + cvt): 256 rows x 4 chunks(8 halfs) = 1024 -> 2/thread
    const float4* gB0[2]; uint32_t dB0[2];
#pragma unroll
    for (int i = 0; i < 2; i++) {
        int idx = tid + 512 * i, r = idx >> 2, c4 = idx & 3;
        gB0[i] = (const float4*)(W + (size_t)(n0 + r) * H_ + c4 * 8);
        dB0[i] = (uint32_t)A_BYTES + (uint32_t)(r * SA + c4 * 4) * 4u;
    }

    float acc[4][4][4];
#pragma unroll
    for (int mf = 0; mf < 4; mf++)
#pragma unroll
        for (int nf = 0; nf < 4; nf++)
#pragma unroll
            for (int q = 0; q < 4; q++) acc[mf][nf][q] = 0.f;

    // prologue: fill stages 0 and 1 (B synchronously, A via cp.async)
#pragma unroll
    for (int s = 0; s < 2; s++) {
        const uint32_t stb = sb + (uint32_t)s * STAGE_BYTES;
        char* stp = smem + (size_t)s * STAGE_BYTES;
#pragma unroll
        for (int i = 0; i < 2; i++) {
            const float4* src = gB0[i] + s * (KCH / 4);
            *(uint4*)(stp + dB0[i]) = pack_half8(src[0], src[1]);
        }
        cp16(stb + dA0, gA0 + s * KCH);
        cp_commit();
    }

    const uint32_t* Sw = (const uint32_t*)smem;
    int slot = 0, fslot = 2;

    for (int kt = 0; kt < NSTEPS; kt++) {
        cp_wait1();
        __syncthreads();       // stage `slot` visible; slot `fslot` free

        // issue fills for kt+2 into fslot: A cp.async + B fp32 LDG (to regs)
        float4 b0a, b0b, b1a, b1b;
        const bool fill = (kt + 2 < NSTEPS);
        if (fill) {
            const uint32_t stb = sb + (uint32_t)fslot * STAGE_BYTES;
            const int o = (kt + 2) * KCH;
            cp16(stb + dA0, gA0 + o);
            const float4* s0 = gB0[0] + (kt + 2) * (KCH / 4);
            const float4* s1 = gB0[1] + (kt + 2) * (KCH / 4);
            b0a = s0[0]; b0b = s0[1];
            b1a = s1[0]; b1b = s1[1];
        }
        cp_commit();

        const uint32_t cur = (uint32_t)slot * STAGE_WORDS;
        const uint32_t bbase = cur + (A_BYTES / 4);
        // 2 k16 sub-steps per stage (words 0..7 and 8..15)
#pragma unroll
        for (int ks = 0; ks < 2; ks++) {
            const int k0 = ks * 8;
            uint32_t af[4][4], bf[4][2];
#pragma unroll
            for (int mf = 0; mf < 4; mf++) {
                const uint32_t r0 = cur + (uint32_t)((wm + mf * 16 + g) * SA + k0 + c);
                af[mf][0] = Sw[r0];
                af[mf][1] = Sw[r0 + 8 * SA];
                af[mf][2] = Sw[r0 + 4];
                af[mf][3] = Sw[r0 + 8 * SA + 4];
            }
#pragma unroll
            for (int nf = 0; nf < 4; nf++) {
                const uint32_t r0 = bbase + (uint32_t)((wn + nf * 8 + g) * SA + k0 + c);
                bf[nf][0] = Sw[r0];
                bf[nf][1] = Sw[r0 + 4];
            }
#pragma unroll
            for (int mf = 0; mf < 4; mf++)
#pragma unroll
                for (int nf = 0; nf < 4; nf++)
                    mma_f16(acc[mf][nf], af[mf], bf[nf]);
        }
        // convert + store B for stage kt+2 (LDG latency covered by compute)
        if (fill) {
            char* stp = smem + (size_t)fslot * STAGE_BYTES;
            *(uint4*)(stp + dB0[0]) = pack_half8(b0a, b0b);
            *(uint4*)(stp + dB0[1]) = pack_half8(b1a, b1b);
        }
        __syncthreads();       // orders B STS + all reads of `slot` before refill
        if (++slot == NSTAGE) slot = 0;
        if (++fslot == NSTAGE) fslot = 0;
    }

    // ---- epilogue: per-row bias + (max, sumexp) over warp's 32 cols ----
    const int tn = blockIdx.y * 8 + wni;
#pragma unroll
    for (int mf = 0; mf < 4; mf++) {
#pragma unroll
        for (int rh = 0; rh < 2; rh++) {
            const int row = m0 + wm + mf * 16 + g + rh * 8;
            float vals[8];
            float mx = -CUDART_INF_F;
#pragma unroll
            for (int nf = 0; nf < 4; nf++)
#pragma unroll
                for (int b = 0; b < 2; b++) {
                    const float v = acc[mf][nf][rh * 2 + b] + sbias[wn + nf * 8 + 2 * c + b];
                    vals[nf * 2 + b] = v;
                    mx = fmaxf(mx, v);
                }
            mx = fmaxf(mx, __shfl_xor_sync(0xffffffffu, mx, 1));
            mx = fmaxf(mx, __shfl_xor_sync(0xffffffffu, mx, 2));
            float s = 0.f;
#pragma unroll
            for (int j = 0; j < 8; j++) s += __expf(vals[j] - mx);
            s += __shfl_xor_sync(0xffffffffu, s, 1);
            s += __shfl_xor_sync(0xffffffffu, s, 2);
            if (c == 0) {
                g_pmax[(size_t)row * NTN + tn] = mx;
                g_psum[(size_t)row * NTN + tn] = s;
            }
        }
    }
}

// ---------------- kernel 2: combine partials, per-token GRPO terms ----------------
__global__ void combine_kernel(const int* __restrict__ amask,
                               const float* __restrict__ adv,
                               const float* __restrict__ ref,
                               const float* __restrict__ oldlp,
                               float* __restrict__ out)
{
    const int warp = threadIdx.x >> 5;
    const int lane = threadIdx.x & 31;
    const int t = blockIdx.x * 8 + warp;
    if (t >= M_) return;

    const float* pm = g_pmax + (size_t)t * NTN;
    const float* ps = g_psum + (size_t)t * NTN;
    float M = -CUDART_INF_F;
    for (int j = lane; j < NTN; j += 32) M = fmaxf(M, pm[j]);
#pragma unroll
    for (int o = 16; o; o >>= 1) M = fmaxf(M, __shfl_xor_sync(0xffffffffu, M, o));
    float S = 0.f;
    for (int j = lane; j < NTN; j += 32) S += ps[j] * expf(pm[j] - M);
#pragma unroll
    for (int o = 16; o; o >>= 1) S += __shfl_xor_sync(0xffffffffu, S, o);

    if (lane == 0) {
        const float lse  = M + logf(S);
        const float logp = g_tok[t] - lse;
        out[1 + t] = logp;

        const float mask = (float)amask[t];
        const float a    = adv[t / T_];
        const float d    = ref[t] - logp;
        const float kl   = expf(d) - d - 1.f;
        const float c1   = expf(logp - oldlp[t]);
        const float c2   = fminf(fmaxf(c1, 0.8f), 1.2f);
        const float l1   = c1 * a, l2 = c2 * a;
        const float ptl  = -(fminf(l1, l2) - 0.04f * kl);
        g_losspt[t] = ptl * mask;
        g_klpt  [t] = kl  * mask;
        g_clippt[t] = (l1 < l2 ? 1.f : 0.f) * mask;
        g_maskpt[t] = mask;
    }
}

// ---------------- kernel 3: deterministic final reductions ----------------
__global__ void finalize_kernel(float* __restrict__ out, int out_size)
{
    __shared__ float sl[1024], sk[1024], sc[1024], sm[1024];
    const int t = threadIdx.x;
    float l = 0.f, k = 0.f, c = 0.f, m = 0.f;
    for (int i = t; i < M_; i += 1024) {
        l += g_losspt[i]; k += g_klpt[i]; c += g_clippt[i]; m += g_maskpt[i];
    }
    sl[t] = l; sk[t] = k; sc[t] = c; sm[t] = m;
    __syncthreads();
    for (int s = 512; s; s >>= 1) {
        if (t < s) { sl[t]+=sl[t+s]; sk[t]+=sk[t+s]; sc[t]+=sc[t+s]; sm[t]+=sm[t+s]; }
        __syncthreads();
    }
    if (t == 0) {
        out[0]      = sl[0] / sm[0];
        out[M_ + 1] = sk[0] / sm[0];
        out[M_ + 2] = sc[0] / sm[0];
    }
    for (int i = M_ + 3 + t; i < out_size; i += 1024) out[i] = 0.f;
}

// ---------------- launch ----------------
extern "C" void kernel_launch(void* const* d_in, const int* in_sizes, int n_in,
                              void* d_out, int out_size)
{
    const float* x     = (const float*)d_in[0];
    const float* w     = (const float*)d_in[1];
    const float* bias  = (const float*)d_in[2];
    const void*  ids   = d_in[3];
    const int*   amask = (const int*)d_in[4];
    const float* adv   = (const float*)d_in[5];
    const float* ref   = (const float*)d_in[6];
    const float* oldlp = (const float*)d_in[7];
    float* out = (float*)d_out;

    cudaFuncSetAttribute(gemm_lse_mma, cudaFuncAttributeMaxDynamicSharedMemorySize,
                         (int)SMEM_TOTAL);

    detect_id64_kernel<<<1, 256>>>((const int*)ids);

    // fp32 -> fp16 copy of X only (W converts in-GEMM)
    {
        __half* xh; cudaGetSymbolAddress((void**)&xh, g_Xh);
        const int xn8 = (M_ * H_) / 8;
        convert_half_kernel<<<(xn8 + 511) / 512, 512>>>(x, xh, xn8);
    }

    tok_logit_kernel<<<M_ / 8, 256>>>(x, w, bias, ids);

    dim3 grid(GRIDM, GRIDN);    // x fast -> consecutive CTAs share W tile in L2
    gemm_lse_mma<<<grid, 512, SMEM_TOTAL>>>(w, bias);

    combine_kernel<<<M_ / 8, 256>>>(amask, adv, ref, oldlp, out);
    finalize_kernel<<<1, 1024>>>(out, out_size);
}

// round 9
// speedup vs baseline: 1.3019x; 1.3019x over previous
#include <cuda_runtime.h>
#include <cuda_fp16.h>
#include <math_constants.h>
#include <cstdint>

// ---------------- problem constants ----------------
#define B_  4
#define T_  1024
#define M_  4096          // B*T tokens
#define H_  2048
#define V_  32000

// ---------------- GEMM tiling ----------------
#define TM  128           // CTA M tile
#define TN  256           // CTA N tile
#define KCH 32            // K elements (halfs) per smem stage
#define NSTEPS (H_/KCH)   // 64
#define NSTAGE 3
#define GRIDM (M_/TM)     // 32
#define GRIDN (V_/TN)     // 125
#define NTN 1000          // 32-col LSE partial tiles (V/32)

#define SA  20            // smem row stride in 32-bit words (16 data + 4 pad)
#define A_WORDS (128*SA)
#define A_BYTES (A_WORDS*4)               // 10240
#define B_BYTES (256*SA*4)                // 20480
#define STAGE_BYTES (A_BYTES + B_BYTES)   // 30720
#define STAGE_WORDS (STAGE_BYTES/4)
#define SM_BIAS (NSTAGE*STAGE_BYTES)      // bias after the 3-stage ring
#define SMEM_TOTAL (SM_BIAS + 256*4)      // 93184

// ---------------- scratch (no allocations allowed) ----------------
__device__ int    g_is64;
__device__ __half g_Wh[(size_t)V_ * H_];   // fp16 weight copy (131 MB)
__device__ __half g_Xh[(size_t)M_ * H_];   // fp16 activation copy (16 MB)
__device__ float  g_pmax[(size_t)M_ * NTN];
__device__ float  g_psum[(size_t)M_ * NTN];
__device__ float  g_tok [M_];
__device__ float  g_losspt[M_];
__device__ float  g_klpt  [M_];
__device__ float  g_clippt[M_];
__device__ float  g_maskpt[M_];

// ---------------- kernel 0: detect int32 vs int64 input_id ----------------
__global__ void detect_id64_kernel(const int* __restrict__ idw) {
    __shared__ int bad;
    if (threadIdx.x == 0) bad = 0;
    __syncthreads();
    int local = 0;
    for (int i = threadIdx.x; i < 2048; i += blockDim.x)
        if (idw[2 * i + 1] != 0) local = 1;
    if (local) atomicOr(&bad, 1);
    __syncthreads();
    if (threadIdx.x == 0) g_is64 = bad ? 0 : 1;
}

// ---------------- kernel 0a: fp32 -> fp16 conversion (8 elems/thread) ----------------
__global__ void convert_half_kernel(const float* __restrict__ src,
                                    __half* __restrict__ dst, int n8)
{
    const int i = blockIdx.x * blockDim.x + threadIdx.x;
    if (i >= n8) return;
    const float4* s = (const float4*)src + 2 * i;
    float4 a = s[0], b = s[1];
    __half2 h[4];
    h[0] = __floats2half2_rn(a.x, a.y);
    h[1] = __floats2half2_rn(a.z, a.w);
    h[2] = __floats2half2_rn(b.x, b.y);
    h[3] = __floats2half2_rn(b.z, b.w);
    *(uint4*)((__half2*)dst + 4 * (size_t)i) = *(uint4*)h;
}

// ---------------- kernel 0b: exact fp32 target-token logits ----------------
__global__ void tok_logit_kernel(const float* __restrict__ X,
                                 const float* __restrict__ W,
                                 const float* __restrict__ bias,
                                 const void* __restrict__ idptr)
{
    const int warp = threadIdx.x >> 5, lane = threadIdx.x & 31;
    const int t = blockIdx.x * 8 + warp;
    if (t >= M_) return;
    const int vid = g_is64 ? (int)((const long long*)idptr)[t]
                           : ((const int*)idptr)[t];
    const float4* xr = (const float4*)(X + (size_t)t * H_);
    const float4* wr = (const float4*)(W + (size_t)vid * H_);
    float s = 0.f;
#pragma unroll 4
    for (int i = lane; i < H_ / 4; i += 32) {
        float4 a = xr[i], b = wr[i];
        s += a.x * b.x + a.y * b.y + a.z * b.z + a.w * b.w;
    }
#pragma unroll
    for (int o = 16; o; o >>= 1) s += __shfl_xor_sync(0xffffffffu, s, o);
    if (lane == 0) g_tok[t] = s + bias[vid];
}

// ---------------- ptx helpers ----------------
__device__ __forceinline__ void mma_f16(float* d, const uint32_t* a, const uint32_t* b) {
    asm volatile(
        "mma.sync.aligned.m16n8k16.row.col.f32.f16.f16.f32 "
        "{%0,%1,%2,%3}, {%4,%5,%6,%7}, {%8,%9}, {%0,%1,%2,%3};"
        : "+f"(d[0]), "+f"(d[1]), "+f"(d[2]), "+f"(d[3])
        : "r"(a[0]), "r"(a[1]), "r"(a[2]), "r"(a[3]), "r"(b[0]), "r"(b[1]));
}
__device__ __forceinline__ void ldsm_x4(uint32_t addr, uint32_t* r) {
    asm volatile("ldmatrix.sync.aligned.m8n8.x4.shared.b16 {%0,%1,%2,%3}, [%4];"
        : "=r"(r[0]), "=r"(r[1]), "=r"(r[2]), "=r"(r[3]) : "r"(addr));
}
__device__ __forceinline__ uint32_t cvta_smem(const void* p) {
    uint32_t a;
    asm("{ .reg .u64 t; cvta.to.shared.u64 t, %1; cvt.u32.u64 %0, t; }" : "=r"(a) : "l"(p));
    return a;
}
__device__ __forceinline__ void cp16(uint32_t dst, const void* src) {
    asm volatile("cp.async.cg.shared.global [%0], [%1], 16;" :: "r"(dst), "l"(src));
}
__device__ __forceinline__ void cp_commit() {
    asm volatile("cp.async.commit_group;" ::: "memory");
}
__device__ __forceinline__ void cp_wait1() {
    asm volatile("cp.async.wait_group 1;" ::: "memory");
}

// ---------------- kernel 1: fp16 mma GEMM + streaming LSE ----------------
// 512 threads (16 warps, warp tile 64x32), 3-stage cp.async pipeline.
// Fragment loads via ldmatrix.x4 (6 LDSM per k16-step vs 24 LDS.32):
// identical fragment values -> bit-identical results to Round 7.
__global__ void __launch_bounds__(512, 1)
gemm_lse_mma(const float* __restrict__ bias)
{
    extern __shared__ char smem[];
    float* sbias = (float*)(smem + SM_BIAS);
    const uint32_t sb = cvta_smem(smem);

    const int tid = threadIdx.x, wid = tid >> 5, lid = tid & 31;
    const int g = lid >> 2, c = lid & 3;
    const int m0 = blockIdx.x * TM, n0 = blockIdx.y * TN;
    const int wm = (wid & 1) * 64;       // warp M offset (0/64)
    const int wni = wid >> 1;            // 0..7
    const int wn = wni * 32;             // warp N offset

    if (tid < 256) sbias[tid] = bias[n0 + tid];

    // ldmatrix lane addressing: lanes 0-7 -> matrix0 rows, 8-15 -> m1,
    // 16-23 -> m2, 24-31 -> m3. For an m16k16 tile: m0=(r0-7,k0-7),
    // m1=(r8-15,k0-7), m2=(r0-7,k8-15), m3=(r8-15,k8-15).
    const int lrow = lid & 7;
    const int lm8  = (lid >> 3) & 1;   // +8 rows for m1/m3
    const int lk8  = (lid >> 4) & 1;   // +8 k-halfs (=4 words) for m2/m3
    // per-thread word offsets within a stage (A region)
    uint32_t aBase[4];
#pragma unroll
    for (int mf = 0; mf < 4; mf++)
        aBase[mf] = (uint32_t)((wm + mf * 16 + lrow + lm8 * 8) * SA + lk8 * 4);
    // B region: nf-pair p covers 16 n-rows
    uint32_t bBase[2];
#pragma unroll
    for (int p = 0; p < 2; p++)
        bBase[p] = (uint32_t)A_WORDS + (uint32_t)((wn + p * 16 + lrow + lm8 * 8) * SA + lk8 * 4);

    // producer addressing (cp.async 16B = 8 halfs each):
    const __half* gA0;  uint32_t dA0;
    const __half* gB0[2]; uint32_t dB0[2];
    {
        int r = tid >> 2, c4 = tid & 3;
        gA0 = g_Xh + (size_t)(m0 + r) * H_ + c4 * 8;
        dA0 = (uint32_t)(r * SA + c4 * 4) * 4u;
    }
#pragma unroll
    for (int i = 0; i < 2; i++) {
        int idx = tid + 512 * i, r = idx >> 2, c4 = idx & 3;
        gB0[i] = g_Wh + (size_t)(n0 + r) * H_ + c4 * 8;
        dB0[i] = (uint32_t)A_BYTES + (uint32_t)(r * SA + c4 * 4) * 4u;
    }

    float acc[4][4][4];
#pragma unroll
    for (int mf = 0; mf < 4; mf++)
#pragma unroll
        for (int nf = 0; nf < 4; nf++)
#pragma unroll
            for (int q = 0; q < 4; q++) acc[mf][nf][q] = 0.f;

    // prologue: fill stages 0 and 1
#pragma unroll
    for (int s = 0; s < 2; s++) {
        const uint32_t stb = sb + (uint32_t)s * STAGE_BYTES;
        cp16(stb + dA0, gA0 + s * KCH);
        cp16(stb + dB0[0], gB0[0] + s * KCH);
        cp16(stb + dB0[1], gB0[1] + s * KCH);
        cp_commit();
    }

    int slot = 0, fslot = 2;

    for (int kt = 0; kt < NSTEPS; kt++) {
        cp_wait1();
        __syncthreads();       // stage `slot` visible; slot `fslot` free

        if (kt + 2 < NSTEPS) {
            const uint32_t stb = sb + (uint32_t)fslot * STAGE_BYTES;
            const int o = (kt + 2) * KCH;
            cp16(stb + dA0, gA0 + o);
            cp16(stb + dB0[0], gB0[0] + o);
            cp16(stb + dB0[1], gB0[1] + o);
        }
        cp_commit();

        const uint32_t curb = sb + (uint32_t)slot * STAGE_BYTES;
        // 2 k16 sub-steps per stage (word offsets 0 and 8)
#pragma unroll
        for (int ks = 0; ks < 2; ks++) {
            const uint32_t k0b = curb + (uint32_t)(ks * 8) * 4u;
            uint32_t af[4][4], bf[4][2];
#pragma unroll
            for (int mf = 0; mf < 4; mf++)
                ldsm_x4(k0b + aBase[mf] * 4u, af[mf]);
#pragma unroll
            for (int p = 0; p < 2; p++) {
                uint32_t r[4];
                ldsm_x4(k0b + bBase[p] * 4u, r);
                bf[2 * p][0] = r[0];  bf[2 * p + 1][0] = r[1];
                bf[2 * p][1] = r[2];  bf[2 * p + 1][1] = r[3];
            }
#pragma unroll
            for (int mf = 0; mf < 4; mf++)
#pragma unroll
                for (int nf = 0; nf < 4; nf++)
                    mma_f16(acc[mf][nf], af[mf], bf[nf]);
        }
        __syncthreads();
        if (++slot == NSTAGE) slot = 0;
        if (++fslot == NSTAGE) fslot = 0;
    }

    // ---- epilogue: per-row bias + (max, sumexp) over warp's 32 cols ----
    const int tn = blockIdx.y * 8 + wni;
#pragma unroll
    for (int mf = 0; mf < 4; mf++) {
#pragma unroll
        for (int rh = 0; rh < 2; rh++) {
            const int row = m0 + wm + mf * 16 + g + rh * 8;
            float vals[8];
            float mx = -CUDART_INF_F;
#pragma unroll
            for (int nf = 0; nf < 4; nf++)
#pragma unroll
                for (int b = 0; b < 2; b++) {
                    const float v = acc[mf][nf][rh * 2 + b] + sbias[wn + nf * 8 + 2 * c + b];
                    vals[nf * 2 + b] = v;
                    mx = fmaxf(mx, v);
                }
            mx = fmaxf(mx, __shfl_xor_sync(0xffffffffu, mx, 1));
            mx = fmaxf(mx, __shfl_xor_sync(0xffffffffu, mx, 2));
            float s = 0.f;
#pragma unroll
            for (int j = 0; j < 8; j++) s += __expf(vals[j] - mx);
            s += __shfl_xor_sync(0xffffffffu, s, 1);
            s += __shfl_xor_sync(0xffffffffu, s, 2);
            if (c == 0) {
                g_pmax[(size_t)row * NTN + tn] = mx;
                g_psum[(size_t)row * NTN + tn] = s;
            }
        }
    }
}

// ---------------- kernel 2: combine partials, per-token GRPO terms ----------------
__global__ void combine_kernel(const int* __restrict__ amask,
                               const float* __restrict__ adv,
                               const float* __restrict__ ref,
                               const float* __restrict__ oldlp,
                               float* __restrict__ out)
{
    const int warp = threadIdx.x >> 5;
    const int lane = threadIdx.x & 31;
    const int t = blockIdx.x * 8 + warp;
    if (t >= M_) return;

    const float* pm = g_pmax + (size_t)t * NTN;
    const float* ps = g_psum + (size_t)t * NTN;
    float M = -CUDART_INF_F;
    for (int j = lane; j < NTN; j += 32) M = fmaxf(M, pm[j]);
#pragma unroll
    for (int o = 16; o; o >>= 1) M = fmaxf(M, __shfl_xor_sync(0xffffffffu, M, o));
    float S = 0.f;
    for (int j = lane; j < NTN; j += 32) S += ps[j] * expf(pm[j] - M);
#pragma unroll
    for (int o = 16; o; o >>= 1) S += __shfl_xor_sync(0xffffffffu, S, o);

    if (lane == 0) {
        const float lse  = M + logf(S);
        const float logp = g_tok[t] - lse;
        out[1 + t] = logp;

        const float mask = (float)amask[t];
        const float a    = adv[t / T_];
        const float d    = ref[t] - logp;
        const float kl   = expf(d) - d - 1.f;
        const float c1   = expf(logp - oldlp[t]);
        const float c2   = fminf(fmaxf(c1, 0.8f), 1.2f);
        const float l1   = c1 * a, l2 = c2 * a;
        const float ptl  = -(fminf(l1, l2) - 0.04f * kl);
        g_losspt[t] = ptl * mask;
        g_klpt  [t] = kl  * mask;
        g_clippt[t] = (l1 < l2 ? 1.f : 0.f) * mask;
        g_maskpt[t] = mask;
    }
}

// ---------------- kernel 3: deterministic final reductions ----------------
__global__ void finalize_kernel(float* __restrict__ out, int out_size)
{
    __shared__ float sl[1024], sk[1024], sc[1024], sm[1024];
    const int t = threadIdx.x;
    float l = 0.f, k = 0.f, c = 0.f, m = 0.f;
    for (int i = t; i < M_; i += 1024) {
        l += g_losspt[i]; k += g_klpt[i]; c += g_clippt[i]; m += g_maskpt[i];
    }
    sl[t] = l; sk[t] = k; sc[t] = c; sm[t] = m;
    __syncthreads();
    for (int s = 512; s; s >>= 1) {
        if (t < s) { sl[t]+=sl[t+s]; sk[t]+=sk[t+s]; sc[t]+=sc[t+s]; sm[t]+=sm[t+s]; }
        __syncthreads();
    }
    if (t == 0) {
        out[0]      = sl[0] / sm[0];
        out[M_ + 1] = sk[0] / sm[0];
        out[M_ + 2] = sc[0] / sm[0];
    }
    for (int i = M_ + 3 + t; i < out_size; i += 1024) out[i] = 0.f;
}

// ---------------- launch ----------------
extern "C" void kernel_launch(void* const* d_in, const int* in_sizes, int n_in,
                              void* d_out, int out_size)
{
    const float* x     = (const float*)d_in[0];
    const float* w     = (const float*)d_in[1];
    const float* bias  = (const float*)d_in[2];
    const void*  ids   = d_in[3];
    const int*   amask = (const int*)d_in[4];
    const float* adv   = (const float*)d_in[5];
    const float* ref   = (const float*)d_in[6];
    const float* oldlp = (const float*)d_in[7];
    float* out = (float*)d_out;

    cudaFuncSetAttribute(gemm_lse_mma, cudaFuncAttributeMaxDynamicSharedMemorySize,
                         (int)SMEM_TOTAL);

    detect_id64_kernel<<<1, 256>>>((const int*)ids);

    // fp32 -> fp16 copies of W and X
    {
        __half* wh; cudaGetSymbolAddress((void**)&wh, g_Wh);
        __half* xh; cudaGetSymbolAddress((void**)&xh, g_Xh);
        const int wn8 = (V_ * H_) / 8, xn8 = (M_ * H_) / 8;
        convert_half_kernel<<<(wn8 + 511) / 512, 512>>>(w, wh, wn8);
        convert_half_kernel<<<(xn8 + 511) / 512, 512>>>(x, xh, xn8);
    }

    tok_logit_kernel<<<M_ / 8, 256>>>(x, w, bias, ids);

    dim3 grid(GRIDM, GRIDN);    // x fast -> consecutive CTAs share W tile in L2
    gemm_lse_mma<<<grid, 512, SMEM_TOTAL>>>(bias);

    combine_kernel<<<M_ / 8, 256>>>(amask, adv, ref, oldlp, out);
    finalize_kernel<<<1, 1024>>>(out, out_size);
}

// round 10
// speedup vs baseline: 1.3173x; 1.0118x over previous
#include <cuda_runtime.h>
#include <cuda_fp16.h>
#include <math_constants.h>
#include <cstdint>

// ---------------- problem constants ----------------
#define B_  4
#define T_  1024
#define M_  4096          // B*T tokens
#define H_  2048
#define V_  32000

// ---------------- GEMM tiling ----------------
#define TM  128           // CTA M tile
#define TN  128           // CTA N tile (halved -> 2 CTAs/SM)
#define KCH 32            // K elements (halfs) per smem stage
#define NSTEPS (H_/KCH)   // 64
#define NSTAGE 3
#define GRIDM (M_/TM)     // 32
#define GRIDN (V_/TN)     // 250
#define NTN 1000          // 32-col LSE partial tiles (V/32)

#define SA  20            // smem row stride in 32-bit words (16 data + 4 pad)
#define A_WORDS (128*SA)
#define A_BYTES (A_WORDS*4)               // 10240
#define B_BYTES (128*SA*4)                // 10240
#define STAGE_BYTES (A_BYTES + B_BYTES)   // 20480
#define SM_BIAS (NSTAGE*STAGE_BYTES)      // bias after the 3-stage ring
#define SMEM_TOTAL (SM_BIAS + 128*4)      // 61952

// ---------------- scratch (no allocations allowed) ----------------
__device__ int    g_is64;
__device__ __half g_Wh[(size_t)V_ * H_];   // fp16 weight copy (131 MB)
__device__ __half g_Xh[(size_t)M_ * H_];   // fp16 activation copy (16 MB)
__device__ float  g_pmax[(size_t)M_ * NTN];
__device__ float  g_psum[(size_t)M_ * NTN];
__device__ float  g_tok [M_];
__device__ float  g_losspt[M_];
__device__ float  g_klpt  [M_];
__device__ float  g_clippt[M_];
__device__ float  g_maskpt[M_];

// ---------------- kernel 0: detect int32 vs int64 input_id ----------------
__global__ void detect_id64_kernel(const int* __restrict__ idw) {
    __shared__ int bad;
    if (threadIdx.x == 0) bad = 0;
    __syncthreads();
    int local = 0;
    for (int i = threadIdx.x; i < 2048; i += blockDim.x)
        if (idw[2 * i + 1] != 0) local = 1;
    if (local) atomicOr(&bad, 1);
    __syncthreads();
    if (threadIdx.x == 0) g_is64 = bad ? 0 : 1;
}

// ---------------- kernel 0a: fp32 -> fp16 conversion (8 elems/thread) ----------------
__global__ void convert_half_kernel(const float* __restrict__ src,
                                    __half* __restrict__ dst, int n8)
{
    const int i = blockIdx.x * blockDim.x + threadIdx.x;
    if (i >= n8) return;
    const float4* s = (const float4*)src + 2 * i;
    float4 a = s[0], b = s[1];
    __half2 h[4];
    h[0] = __floats2half2_rn(a.x, a.y);
    h[1] = __floats2half2_rn(a.z, a.w);
    h[2] = __floats2half2_rn(b.x, b.y);
    h[3] = __floats2half2_rn(b.z, b.w);
    *(uint4*)((__half2*)dst + 4 * (size_t)i) = *(uint4*)h;
}

// ---------------- kernel 0b: exact fp32 target-token logits ----------------
__global__ void tok_logit_kernel(const float* __restrict__ X,
                                 const float* __restrict__ W,
                                 const float* __restrict__ bias,
                                 const void* __restrict__ idptr)
{
    const int warp = threadIdx.x >> 5, lane = threadIdx.x & 31;
    const int t = blockIdx.x * 8 + warp;
    if (t >= M_) return;
    const int vid = g_is64 ? (int)((const long long*)idptr)[t]
                           : ((const int*)idptr)[t];
    const float4* xr = (const float4*)(X + (size_t)t * H_);
    const float4* wr = (const float4*)(W + (size_t)vid * H_);
    float s = 0.f;
#pragma unroll 4
    for (int i = lane; i < H_ / 4; i += 32) {
        float4 a = xr[i], b = wr[i];
        s += a.x * b.x + a.y * b.y + a.z * b.z + a.w * b.w;
    }
#pragma unroll
    for (int o = 16; o; o >>= 1) s += __shfl_xor_sync(0xffffffffu, s, o);
    if (lane == 0) g_tok[t] = s + bias[vid];
}

// ---------------- ptx helpers ----------------
__device__ __forceinline__ void mma_f16(float* d, const uint32_t* a, const uint32_t* b) {
    asm volatile(
        "mma.sync.aligned.m16n8k16.row.col.f32.f16.f16.f32 "
        "{%0,%1,%2,%3}, {%4,%5,%6,%7}, {%8,%9}, {%0,%1,%2,%3};"
        : "+f"(d[0]), "+f"(d[1]), "+f"(d[2]), "+f"(d[3])
        : "r"(a[0]), "r"(a[1]), "r"(a[2]), "r"(a[3]), "r"(b[0]), "r"(b[1]));
}
__device__ __forceinline__ void ldsm_x4(uint32_t addr, uint32_t* r) {
    asm volatile("ldmatrix.sync.aligned.m8n8.x4.shared.b16 {%0,%1,%2,%3}, [%4];"
        : "=r"(r[0]), "=r"(r[1]), "=r"(r[2]), "=r"(r[3]) : "r"(addr));
}
__device__ __forceinline__ uint32_t cvta_smem(const void* p) {
    uint32_t a;
    asm("{ .reg .u64 t; cvta.to.shared.u64 t, %1; cvt.u32.u64 %0, t; }" : "=r"(a) : "l"(p));
    return a;
}
__device__ __forceinline__ void cp16(uint32_t dst, const void* src) {
    asm volatile("cp.async.cg.shared.global [%0], [%1], 16;" :: "r"(dst), "l"(src));
}
__device__ __forceinline__ void cp_commit() {
    asm volatile("cp.async.commit_group;" ::: "memory");
}
__device__ __forceinline__ void cp_wait1() {
    asm volatile("cp.async.wait_group 1;" ::: "memory");
}

// ---------------- kernel 1: fp16 mma GEMM + streaming LSE ----------------
// 256 threads (8 warps, warp tile 64x32), 3-stage cp.async pipeline,
// ldmatrix fragment loads. TN=128 so two CTAs co-reside per SM: barrier
// bubbles in one CTA overlap the other's HMMAs.
__global__ void __launch_bounds__(256, 2)
gemm_lse_mma(const float* __restrict__ bias)
{
    extern __shared__ char smem[];
    float* sbias = (float*)(smem + SM_BIAS);
    const uint32_t sb = cvta_smem(smem);

    const int tid = threadIdx.x, wid = tid >> 5, lid = tid & 31;
    const int g = lid >> 2, c = lid & 3;
    const int m0 = blockIdx.x * TM, n0 = blockIdx.y * TN;
    const int wm = (wid & 1) * 64;       // warp M offset (0/64)
    const int wni = wid >> 1;            // 0..3
    const int wn = wni * 32;             // warp N offset

    if (tid < 128) sbias[tid] = bias[n0 + tid];

    // ldmatrix addressing (m16k16 tile = 4 8x8 matrices)
    const int lrow = lid & 7;
    const int lm8  = (lid >> 3) & 1;
    const int lk8  = (lid >> 4) & 1;
    uint32_t aBase[4];
#pragma unroll
    for (int mf = 0; mf < 4; mf++)
        aBase[mf] = (uint32_t)((wm + mf * 16 + lrow + lm8 * 8) * SA + lk8 * 4);
    uint32_t bBase[2];
#pragma unroll
    for (int p = 0; p < 2; p++)
        bBase[p] = (uint32_t)A_WORDS + (uint32_t)((wn + p * 16 + lrow + lm8 * 8) * SA + lk8 * 4);

    // producers: A and B each 128 rows x 4 chunks = 512 cp16 -> 2/thread each
    const __half* gA0[2]; uint32_t dA0[2];
    const __half* gB0[2]; uint32_t dB0[2];
#pragma unroll
    for (int i = 0; i < 2; i++) {
        int idx = tid + 256 * i, r = idx >> 2, c4 = idx & 3;
        gA0[i] = g_Xh + (size_t)(m0 + r) * H_ + c4 * 8;
        dA0[i] = (uint32_t)(r * SA + c4 * 4) * 4u;
        gB0[i] = g_Wh + (size_t)(n0 + r) * H_ + c4 * 8;
        dB0[i] = (uint32_t)A_BYTES + (uint32_t)(r * SA + c4 * 4) * 4u;
    }

    float acc[4][4][4];
#pragma unroll
    for (int mf = 0; mf < 4; mf++)
#pragma unroll
        for (int nf = 0; nf < 4; nf++)
#pragma unroll
            for (int q = 0; q < 4; q++) acc[mf][nf][q] = 0.f;

    // prologue: fill stages 0 and 1
#pragma unroll
    for (int s = 0; s < 2; s++) {
        const uint32_t stb = sb + (uint32_t)s * STAGE_BYTES;
#pragma unroll
        for (int i = 0; i < 2; i++) {
            cp16(stb + dA0[i], gA0[i] + s * KCH);
            cp16(stb + dB0[i], gB0[i] + s * KCH);
        }
        cp_commit();
    }

    int slot = 0, fslot = 2;

    for (int kt = 0; kt < NSTEPS; kt++) {
        cp_wait1();
        __syncthreads();       // stage `slot` visible; slot `fslot` free

        if (kt + 2 < NSTEPS) {
            const uint32_t stb = sb + (uint32_t)fslot * STAGE_BYTES;
            const int o = (kt + 2) * KCH;
#pragma unroll
            for (int i = 0; i < 2; i++) {
                cp16(stb + dA0[i], gA0[i] + o);
                cp16(stb + dB0[i], gB0[i] + o);
            }
        }
        cp_commit();

        const uint32_t curb = sb + (uint32_t)slot * STAGE_BYTES;
#pragma unroll
        for (int ks = 0; ks < 2; ks++) {
            const uint32_t k0b = curb + (uint32_t)(ks * 8) * 4u;
            uint32_t af[4][4], bf[4][2];
#pragma unroll
            for (int mf = 0; mf < 4; mf++)
                ldsm_x4(k0b + aBase[mf] * 4u, af[mf]);
#pragma unroll
            for (int p = 0; p < 2; p++) {
                uint32_t r[4];
                ldsm_x4(k0b + bBase[p] * 4u, r);
                bf[2 * p][0] = r[0];  bf[2 * p + 1][0] = r[1];
                bf[2 * p][1] = r[2];  bf[2 * p + 1][1] = r[3];
            }
#pragma unroll
            for (int mf = 0; mf < 4; mf++)
#pragma unroll
                for (int nf = 0; nf < 4; nf++)
                    mma_f16(acc[mf][nf], af[mf], bf[nf]);
        }
        __syncthreads();
        if (++slot == NSTAGE) slot = 0;
        if (++fslot == NSTAGE) fslot = 0;
    }

    // ---- epilogue: per-row bias + (max, sumexp) over warp's 32 cols ----
    const int tn = blockIdx.y * 4 + wni;
#pragma unroll
    for (int mf = 0; mf < 4; mf++) {
#pragma unroll
        for (int rh = 0; rh < 2; rh++) {
            const int row = m0 + wm + mf * 16 + g + rh * 8;
            float vals[8];
            float mx = -CUDART_INF_F;
#pragma unroll
            for (int nf = 0; nf < 4; nf++)
#pragma unroll
                for (int b = 0; b < 2; b++) {
                    const float v = acc[mf][nf][rh * 2 + b] + sbias[wn + nf * 8 + 2 * c + b];
                    vals[nf * 2 + b] = v;
                    mx = fmaxf(mx, v);
                }
            mx = fmaxf(mx, __shfl_xor_sync(0xffffffffu, mx, 1));
            mx = fmaxf(mx, __shfl_xor_sync(0xffffffffu, mx, 2));
            float s = 0.f;
#pragma unroll
            for (int j = 0; j < 8; j++) s += __expf(vals[j] - mx);
            s += __shfl_xor_sync(0xffffffffu, s, 1);
            s += __shfl_xor_sync(0xffffffffu, s, 2);
            if (c == 0) {
                g_pmax[(size_t)row * NTN + tn] = mx;
                g_psum[(size_t)row * NTN + tn] = s;
            }
        }
    }
}

// ---------------- kernel 2: combine partials, per-token GRPO terms ----------------
__global__ void combine_kernel(const int* __restrict__ amask,
                               const float* __restrict__ adv,
                               const float* __restrict__ ref,
                               const float* __restrict__ oldlp,
                               float* __restrict__ out)
{
    const int warp = threadIdx.x >> 5;
    const int lane = threadIdx.x & 31;
    const int t = blockIdx.x * 8 + warp;
    if (t >= M_) return;

    const float* pm = g_pmax + (size_t)t * NTN;
    const float* ps = g_psum + (size_t)t * NTN;
    float M = -CUDART_INF_F;
    for (int j = lane; j < NTN; j += 32) M = fmaxf(M, pm[j]);
#pragma unroll
    for (int o = 16; o; o >>= 1) M = fmaxf(M, __shfl_xor_sync(0xffffffffu, M, o));
    float S = 0.f;
    for (int j = lane; j < NTN; j += 32) S += ps[j] * expf(pm[j] - M);
#pragma unroll
    for (int o = 16; o; o >>= 1) S += __shfl_xor_sync(0xffffffffu, S, o);

    if (lane == 0) {
        const float lse  = M + logf(S);
        const float logp = g_tok[t] - lse;
        out[1 + t] = logp;

        const float mask = (float)amask[t];
        const float a    = adv[t / T_];
        const float d    = ref[t] - logp;
        const float kl   = expf(d) - d - 1.f;
        const float c1   = expf(logp - oldlp[t]);
        const float c2   = fminf(fmaxf(c1, 0.8f), 1.2f);
        const float l1   = c1 * a, l2 = c2 * a;
        const float ptl  = -(fminf(l1, l2) - 0.04f * kl);
        g_losspt[t] = ptl * mask;
        g_klpt  [t] = kl  * mask;
        g_clippt[t] = (l1 < l2 ? 1.f : 0.f) * mask;
        g_maskpt[t] = mask;
    }
}

// ---------------- kernel 3: deterministic final reductions ----------------
__global__ void finalize_kernel(float* __restrict__ out, int out_size)
{
    __shared__ float sl[1024], sk[1024], sc[1024], sm[1024];
    const int t = threadIdx.x;
    float l = 0.f, k = 0.f, c = 0.f, m = 0.f;
    for (int i = t; i < M_; i += 1024) {
        l += g_losspt[i]; k += g_klpt[i]; c += g_clippt[i]; m += g_maskpt[i];
    }
    sl[t] = l; sk[t] = k; sc[t] = c; sm[t] = m;
    __syncthreads();
    for (int s = 512; s; s >>= 1) {
        if (t < s) { sl[t]+=sl[t+s]; sk[t]+=sk[t+s]; sc[t]+=sc[t+s]; sm[t]+=sm[t+s]; }
        __syncthreads();
    }
    if (t == 0) {
        out[0]      = sl[0] / sm[0];
        out[M_ + 1] = sk[0] / sm[0];
        out[M_ + 2] = sc[0] / sm[0];
    }
    for (int i = M_ + 3 + t; i < out_size; i += 1024) out[i] = 0.f;
}

// ---------------- launch ----------------
extern "C" void kernel_launch(void* const* d_in, const int* in_sizes, int n_in,
                              void* d_out, int out_size)
{
    const float* x     = (const float*)d_in[0];
    const float* w     = (const float*)d_in[1];
    const float* bias  = (const float*)d_in[2];
    const void*  ids   = d_in[3];
    const int*   amask = (const int*)d_in[4];
    const float* adv   = (const float*)d_in[5];
    const float* ref   = (const float*)d_in[6];
    const float* oldlp = (const float*)d_in[7];
    float* out = (float*)d_out;

    cudaFuncSetAttribute(gemm_lse_mma, cudaFuncAttributeMaxDynamicSharedMemorySize,
                         (int)SMEM_TOTAL);

    detect_id64_kernel<<<1, 256>>>((const int*)ids);

    // fp32 -> fp16 copies of W and X
    {
        __half* wh; cudaGetSymbolAddress((void**)&wh, g_Wh);
        __half* xh; cudaGetSymbolAddress((void**)&xh, g_Xh);
        const int wn8 = (V_ * H_) / 8, xn8 = (M_ * H_) / 8;
        convert_half_kernel<<<(wn8 + 511) / 512, 512>>>(w, wh, wn8);
        convert_half_kernel<<<(xn8 + 511) / 512, 512>>>(x, xh, xn8);
    }

    tok_logit_kernel<<<M_ / 8, 256>>>(x, w, bias, ids);

    dim3 grid(GRIDM, GRIDN);    // x fast -> consecutive CTAs share W tile in L2
    gemm_lse_mma<<<grid, 256, SMEM_TOTAL>>>(bias);

    combine_kernel<<<M_ / 8, 256>>>(amask, adv, ref, oldlp, out);
    finalize_kernel<<<1, 1024>>>(out, out_size);
}